// round 11
// baseline (speedup 1.0000x reference)
#include <cuda_runtime.h>

#define MB 32
#define NP 256
#define QP (NP / 2)
#define ND 512
#define NPAIR (MB * (MB - 1) / 2)   // 496 unordered pairs i<j

// scratch (no allocations allowed)
__device__ float g_D[MB * MB];      // D(i,j) = mean_p min_q d2
__device__ float g_phat[MB * MB];   // softmax(inner_dot) rows, precomputed

// ---- packed f32x2 helpers (Blackwell FFMA2 path) ---------------------------
__device__ __forceinline__ unsigned long long pack2(float lo, float hi) {
    unsigned long long r;
    asm("mov.b64 %0, {%1, %2};" : "=l"(r) : "f"(lo), "f"(hi));
    return r;
}
__device__ __forceinline__ unsigned long long fma2(unsigned long long a,
                                                   unsigned long long b,
                                                   unsigned long long c) {
    unsigned long long d;
    asm("fma.rn.f32x2 %0, %1, %2, %3;" : "=l"(d) : "l"(a), "l"(b), "l"(c));
    return d;
}
__device__ __forceinline__ void unpack2(unsigned long long v, float& lo, float& hi) {
    asm("mov.b64 {%0, %1}, %2;" : "=f"(lo), "=f"(hi) : "l"(v));
}

// pair index b -> (i,j), i<j, row-major upper triangle
__device__ __forceinline__ void pair_from_index(int b, int& i, int& j) {
    // i = largest such that i*(2*MB-i-1)/2 <= b
    float bf = (float)b;
    int ii = (int)(MB - 0.5f - sqrtf((MB - 0.5f) * (MB - 0.5f) - 2.0f * bf));
    // fix up rounding
    while ((ii + 1) * (2 * MB - ii - 2) / 2 <= b) ii++;
    while (ii * (2 * MB - ii - 1) / 2 > b) ii--;
    i = ii;
    j = b - ii * (2 * MB - ii - 1) / 2 + ii + 1;
}

// ---------------------------------------------------------------------------
// Kernel A, flat grid of 528 blocks x 256 threads:
//   blocks [0,496): chamfer both directions for unordered pair {i<j}
//   blocks [496,528): inner_dot row i + softmax -> g_phat row; g_D[i][i]=0
// ---------------------------------------------------------------------------
__global__ void fused_A_kernel(const float* __restrict__ xyz,
                               const float* __restrict__ emb) {
    const int b = blockIdx.x;
    const int t = threadIdx.x;          // 0..255
    const int w = t >> 5, lane = t & 31;

    if (b < NPAIR) {
        // ---------------- chamfer part, pair {i<j} ----------------
        int i, j;
        pair_from_index(b, i, j);

        __shared__ float4 s_i[2 * QP];
        __shared__ float4 s_jj[2 * QP];
        __shared__ float  s_redA[8];
        __shared__ float  s_redB[8];

        const float* shapes = xyz + MB * NP * 3;

        // stage both shapes, pair-interleaved SoA: {x0,x1,y0,y1}|{z0,z1,w0,w1}
        {
            const float* pi = shapes + (i * NP + t) * 3;
            float x = pi[0], y = pi[1], z = pi[2];
            float ww = x * x + y * y + z * z;
            float* base = reinterpret_cast<float*>(&s_i[(t >> 1) * 2]);
            int s = t & 1;
            base[0 + s] = x; base[2 + s] = y; base[4 + s] = z; base[6 + s] = ww;

            const float* pj = shapes + (j * NP + t) * 3;
            float xb = pj[0], yb = pj[1], zb = pj[2];
            float wb = xb * xb + yb * yb + zb * zb;
            float* baseb = reinterpret_cast<float*>(&s_jj[(t >> 1) * 2]);
            baseb[0 + s] = xb; baseb[2 + s] = yb; baseb[4 + s] = zb; baseb[6 + s] = wb;

            // my two roles' points (reuse the loaded values)
            // role A: point t of shape i vs all q in j
            // role B: point t of shape j vs all p in i
        }

        const float* pi = shapes + (i * NP + t) * 3;
        float ax = pi[0], ay = pi[1], az = pi[2];
        const float awv = ax * ax + ay * ay + az * az;
        const unsigned long long a2x = pack2(-2.f * ax, -2.f * ax);
        const unsigned long long a2y = pack2(-2.f * ay, -2.f * ay);
        const unsigned long long a2z = pack2(-2.f * az, -2.f * az);

        const float* pj = shapes + (j * NP + t) * 3;
        float bx = pj[0], by = pj[1], bz = pj[2];
        const float bwv = bx * bx + by * by + bz * bz;
        const unsigned long long b2x = pack2(-2.f * bx, -2.f * bx);
        const unsigned long long b2y = pack2(-2.f * by, -2.f * by);
        const unsigned long long b2z = pack2(-2.f * bz, -2.f * bz);

        __syncthreads();

        const float INF = 3.4e38f;
        float mAlo = INF, mAhi = INF, mBlo = INF, mBhi = INF;

        const ulonglong2* si64 = reinterpret_cast<const ulonglong2*>(s_i);
        const ulonglong2* sj64 = reinterpret_cast<const ulonglong2*>(s_jj);

#pragma unroll 4
        for (int qp = 0; qp < QP; qp++) {
            // role A: a vs q-pair of shape j
            ulonglong2 xyj = sj64[2 * qp + 0];
            ulonglong2 zwj = sj64[2 * qp + 1];
            unsigned long long sA =
                fma2(a2x, xyj.x, fma2(a2y, xyj.y, fma2(a2z, zwj.x, zwj.y)));
            // role B: b vs p-pair of shape i
            ulonglong2 xyi = si64[2 * qp + 0];
            ulonglong2 zwi = si64[2 * qp + 1];
            unsigned long long sB =
                fma2(b2x, xyi.x, fma2(b2y, xyi.y, fma2(b2z, zwi.x, zwi.y)));
            float la, ha, lb, hb;
            unpack2(sA, la, ha);
            unpack2(sB, lb, hb);
            mAlo = fminf(mAlo, la);
            mAhi = fminf(mAhi, ha);
            mBlo = fminf(mBlo, lb);
            mBhi = fminf(mBhi, hb);
        }

        float sA = fminf(mAlo, mAhi) + awv;   // contributes to D(i,j)
        float sB = fminf(mBlo, mBhi) + bwv;   // contributes to D(j,i)
#pragma unroll
        for (int o = 16; o > 0; o >>= 1) {
            sA += __shfl_down_sync(0xffffffffu, sA, o);
            sB += __shfl_down_sync(0xffffffffu, sB, o);
        }
        if (lane == 0) { s_redA[w] = sA; s_redB[w] = sB; }
        __syncthreads();
        if (t == 0) {
            float tA = 0.f, tB = 0.f;
#pragma unroll
            for (int k = 0; k < 8; k++) { tA += s_redA[k]; tB += s_redB[k]; }
            g_D[i * MB + j] = tA * (1.f / NP);
            g_D[j * MB + i] = tB * (1.f / NP);
        }
    } else {
        // ---------------- inner_dot row + p_hat softmax ----------------
        const int i = b - NPAIR;
        __shared__ float s_dot[MB];

        // keep my slice of emb row i in registers, reuse for all j
        float eir[16];
        float ni = 0.f;
#pragma unroll
        for (int u = 0; u < 16; u++) {
            float e = emb[i * ND + u * 32 + lane];
            eir[u] = e;
            ni += e * e;
        }
#pragma unroll
        for (int o = 16; o > 0; o >>= 1) ni += __shfl_xor_sync(0xffffffffu, ni, o);
        const float inv_ni = rsqrtf(ni);

        for (int j = w; j < MB; j += 8) {
            const float* ej = emb + (MB + j) * ND;
            float dot = 0.f, nj = 0.f;
#pragma unroll
            for (int u = 0; u < 16; u++) {
                float e = ej[u * 32 + lane];
                dot += e * eir[u];
                nj += e * e;
            }
#pragma unroll
            for (int o = 16; o > 0; o >>= 1) {
                dot += __shfl_down_sync(0xffffffffu, dot, o);
                nj  += __shfl_down_sync(0xffffffffu, nj, o);
            }
            if (lane == 0) s_dot[j] = dot * rsqrtf(nj) * inv_ni;
        }
        // diagonal of g_D is never written by pair blocks; it is exactly 0
        if (t == 32) g_D[i * MB + i] = 0.0f;
        __syncthreads();

        // warp 0: softmax over the 32 dots -> p_hat row
        if (w == 0) {
            float idot = s_dot[lane];
            float m = idot;
#pragma unroll
            for (int o = 16; o > 0; o >>= 1) m = fmaxf(m, __shfl_xor_sync(0xffffffffu, m, o));
            float e = expf(idot - m);
            float sum = e;
#pragma unroll
            for (int o = 16; o > 0; o >>= 1) sum += __shfl_xor_sync(0xffffffffu, sum, o);
            g_phat[i * MB + lane] = e / sum;
        }
    }
}

// ---------------------------------------------------------------------------
// Kernel B: 1 block x 1024 threads, PDL-launched. Warp i handles row i:
// cd softmax -> p; |p_hat - p| row sum. Warp 0 does the final sum.
// ---------------------------------------------------------------------------
__global__ void final_B_kernel(float* __restrict__ out) {
    cudaGridDependencySynchronize();

    __shared__ float s_row[MB];
    const int i = threadIdx.x >> 5, lane = threadIdx.x & 31;

    {
        float p_hat = g_phat[i * MB + lane];

        const float SIG = 1.0f * 0.997f / 3.0f;
        const float INV2S2 = 1.0f / (2.0f * SIG * SIG);
        float cd = g_D[i * MB + lane] + g_D[lane * MB + i];
        float nd = -(cd * cd) * INV2S2;
        float m2 = nd;
#pragma unroll
        for (int o = 16; o > 0; o >>= 1) m2 = fmaxf(m2, __shfl_xor_sync(0xffffffffu, m2, o));
        float e2 = expf(nd - m2);
        float sum2 = e2;
#pragma unroll
        for (int o = 16; o > 0; o >>= 1) sum2 += __shfl_xor_sync(0xffffffffu, sum2, o);
        float p = e2 / sum2;

        float diff = fabsf(p_hat - p);
#pragma unroll
        for (int o = 16; o > 0; o >>= 1) diff += __shfl_xor_sync(0xffffffffu, diff, o);
        if (lane == 0) s_row[i] = diff;
    }
    __syncthreads();

    if (i == 0) {
        float v = s_row[lane];
#pragma unroll
        for (int o = 16; o > 0; o >>= 1) v += __shfl_down_sync(0xffffffffu, v, o);
        if (lane == 0) out[0] = v * (1.0f / (MB * MB));
    }
}

extern "C" void kernel_launch(void* const* d_in, const int* in_sizes, int n_in,
                              void* d_out, int out_size) {
    const float* embeddings = (const float*)d_in[0];  // (64, 512) fp32
    const float* xyz        = (const float*)d_in[1];  // (64, 256, 3) fp32
    float* out = (float*)d_out;

    fused_A_kernel<<<NPAIR + MB, 256>>>(xyz, embeddings);

    // PDL launch of the epilogue: overlaps its launch latency with A's tail.
    cudaLaunchConfig_t cfg = {};
    cfg.gridDim  = dim3(1, 1, 1);
    cfg.blockDim = dim3(MB * 32, 1, 1);
    cfg.dynamicSmemBytes = 0;
    cfg.stream = 0;
    cudaLaunchAttribute attr;
    attr.id = cudaLaunchAttributeProgrammaticStreamSerialization;
    attr.val.programmaticStreamSerializationAllowed = 1;
    cfg.attrs = &attr;
    cfg.numAttrs = 1;
    cudaLaunchKernelEx(&cfg, final_B_kernel, out);
}

// round 13
// speedup vs baseline: 1.1000x; 1.1000x over previous
#include <cuda_runtime.h>

#define MB 32
#define NP 256
#define QP (NP / 2)
#define ND 512

// scratch (no allocations allowed)
__device__ float g_D[MB * MB];      // D(i,j) = mean_p min_q d2
__device__ float g_phat[MB * MB];   // softmax(inner_dot) rows, precomputed

// ---- packed f32x2 helpers (Blackwell FFMA2 path) ---------------------------
__device__ __forceinline__ unsigned long long pack2(float lo, float hi) {
    unsigned long long r;
    asm("mov.b64 %0, {%1, %2};" : "=l"(r) : "f"(lo), "f"(hi));
    return r;
}
__device__ __forceinline__ unsigned long long fma2(unsigned long long a,
                                                   unsigned long long b,
                                                   unsigned long long c) {
    unsigned long long d;
    asm("fma.rn.f32x2 %0, %1, %2, %3;" : "=l"(d) : "l"(a), "l"(b), "l"(c));
    return d;
}
__device__ __forceinline__ void unpack2(unsigned long long v, float& lo, float& hi) {
    asm("mov.b64 {%0, %1}, %2;" : "=f"(lo), "=f"(hi) : "l"(v));
}

// ---------------------------------------------------------------------------
// Kernel A, flat grid of 1056 blocks x 256 threads:
//   blocks [0,1024): chamfer D(i,j), ordered pair (i = b>>5, j = b&31)
//                    one a-point per thread (P=1), 8 warps -> ~89% occupancy
//   blocks [1024,1056): inner_dot row i + softmax -> g_phat row
// ---------------------------------------------------------------------------
__global__ void fused_A_kernel(const float* __restrict__ xyz,
                               const float* __restrict__ emb) {
    const int b = blockIdx.x;
    const int t = threadIdx.x;          // 0..255
    const int w = t >> 5, lane = t & 31;

    if (b < MB * MB) {
        // ---------------- chamfer part ----------------
        const int i = b >> 5, j = b & 31;
        __shared__ float4 s_j[2 * QP];
        __shared__ float  s_red[8];

        const float* shapes = xyz + MB * NP * 3;

        // stage shape j pair-interleaved SoA: {x0,x1,y0,y1} | {z0,z1,w0,w1}
        {
            const float* p = shapes + (j * NP + t) * 3;
            float x = p[0], y = p[1], z = p[2];
            float ww = x * x + y * y + z * z;
            float* base = reinterpret_cast<float*>(&s_j[(t >> 1) * 2]);
            int s = t & 1;
            base[0 + s] = x;
            base[2 + s] = y;
            base[4 + s] = z;
            base[6 + s] = ww;
        }

        // my single a-point, pre-scaled by -2, splatted to f32x2
        const float* p = shapes + (i * NP + t) * 3;
        float ax = p[0], ay = p[1], az = p[2];
        const float aw = ax * ax + ay * ay + az * az;
        const unsigned long long a2x = pack2(-2.f * ax, -2.f * ax);
        const unsigned long long a2y = pack2(-2.f * ay, -2.f * ay);
        const unsigned long long a2z = pack2(-2.f * az, -2.f * az);

        __syncthreads();

        const float INF = 3.4e38f;
        float mlo = INF, mhi = INF;

        const ulonglong2* sj64 = reinterpret_cast<const ulonglong2*>(s_j);

#pragma unroll 4
        for (int qp = 0; qp < QP; qp++) {
            ulonglong2 xy = sj64[2 * qp + 0];  // {x01, y01}
            ulonglong2 zw = sj64[2 * qp + 1];  // {z01, w01}
            unsigned long long s =
                fma2(a2x, xy.x, fma2(a2y, xy.y, fma2(a2z, zw.x, zw.y)));
            float lo, hi;
            unpack2(s, lo, hi);
            mlo = fminf(mlo, lo);
            mhi = fminf(mhi, hi);
        }

        float s = fminf(mlo, mhi) + aw;
#pragma unroll
        for (int o = 16; o > 0; o >>= 1) s += __shfl_down_sync(0xffffffffu, s, o);
        if (lane == 0) s_red[w] = s;
        __syncthreads();
        if (t == 0) {
            float tot = 0.f;
#pragma unroll
            for (int k = 0; k < 8; k++) tot += s_red[k];
            g_D[i * MB + j] = tot * (1.f / NP);
        }
    } else {
        // ---------------- inner_dot row + p_hat softmax ----------------
        const int i = b - MB * MB;
        __shared__ float s_dot[MB];

        // keep my slice of emb row i in registers, reuse for all j
        float eir[16];
        float ni = 0.f;
#pragma unroll
        for (int u = 0; u < 16; u++) {
            float e = emb[i * ND + u * 32 + lane];
            eir[u] = e;
            ni += e * e;
        }
#pragma unroll
        for (int o = 16; o > 0; o >>= 1) ni += __shfl_xor_sync(0xffffffffu, ni, o);
        const float inv_ni = rsqrtf(ni);

        for (int j = w; j < MB; j += 8) {
            const float* ej = emb + (MB + j) * ND;
            float dot = 0.f, nj = 0.f;
#pragma unroll
            for (int u = 0; u < 16; u++) {
                float e = ej[u * 32 + lane];
                dot += e * eir[u];
                nj += e * e;
            }
#pragma unroll
            for (int o = 16; o > 0; o >>= 1) {
                dot += __shfl_down_sync(0xffffffffu, dot, o);
                nj  += __shfl_down_sync(0xffffffffu, nj, o);
            }
            if (lane == 0) s_dot[j] = dot * rsqrtf(nj) * inv_ni;
        }
        __syncthreads();

        // warp 0: softmax over the 32 dots -> p_hat row
        if (w == 0) {
            float idot = s_dot[lane];
            float m = idot;
#pragma unroll
            for (int o = 16; o > 0; o >>= 1) m = fmaxf(m, __shfl_xor_sync(0xffffffffu, m, o));
            float e = expf(idot - m);
            float sum = e;
#pragma unroll
            for (int o = 16; o > 0; o >>= 1) sum += __shfl_xor_sync(0xffffffffu, sum, o);
            g_phat[i * MB + lane] = e / sum;
        }
    }
}

// ---------------------------------------------------------------------------
// Kernel B: 1 block x 1024 threads, PDL-launched. Warp i handles row i:
// cd softmax -> p; |p_hat - p| row sum. Warp 0 does the final sum.
// ---------------------------------------------------------------------------
__global__ void final_B_kernel(float* __restrict__ out) {
    cudaGridDependencySynchronize();

    __shared__ float s_row[MB];
    const int i = threadIdx.x >> 5, lane = threadIdx.x & 31;

    {
        float p_hat = g_phat[i * MB + lane];

        const float SIG = 1.0f * 0.997f / 3.0f;
        const float INV2S2 = 1.0f / (2.0f * SIG * SIG);
        float cd = g_D[i * MB + lane] + g_D[lane * MB + i];
        float nd = -(cd * cd) * INV2S2;
        float m2 = nd;
#pragma unroll
        for (int o = 16; o > 0; o >>= 1) m2 = fmaxf(m2, __shfl_xor_sync(0xffffffffu, m2, o));
        float e2 = expf(nd - m2);
        float sum2 = e2;
#pragma unroll
        for (int o = 16; o > 0; o >>= 1) sum2 += __shfl_xor_sync(0xffffffffu, sum2, o);
        float p = e2 / sum2;

        float diff = fabsf(p_hat - p);
#pragma unroll
        for (int o = 16; o > 0; o >>= 1) diff += __shfl_xor_sync(0xffffffffu, diff, o);
        if (lane == 0) s_row[i] = diff;
    }
    __syncthreads();

    if (i == 0) {
        float v = s_row[lane];
#pragma unroll
        for (int o = 16; o > 0; o >>= 1) v += __shfl_down_sync(0xffffffffu, v, o);
        if (lane == 0) out[0] = v * (1.0f / (MB * MB));
    }
}

extern "C" void kernel_launch(void* const* d_in, const int* in_sizes, int n_in,
                              void* d_out, int out_size) {
    const float* embeddings = (const float*)d_in[0];  // (64, 512) fp32
    const float* xyz        = (const float*)d_in[1];  // (64, 256, 3) fp32
    float* out = (float*)d_out;

    fused_A_kernel<<<MB * MB + MB, 256>>>(xyz, embeddings);

    // PDL launch of the epilogue: overlaps its launch latency with A's tail.
    cudaLaunchConfig_t cfg = {};
    cfg.gridDim  = dim3(1, 1, 1);
    cfg.blockDim = dim3(MB * 32, 1, 1);
    cfg.dynamicSmemBytes = 0;
    cfg.stream = 0;
    cudaLaunchAttribute attr;
    attr.id = cudaLaunchAttributeProgrammaticStreamSerialization;
    attr.val.programmaticStreamSerializationAllowed = 1;
    cfg.attrs = &attr;
    cfg.numAttrs = 1;
    cudaLaunchKernelEx(&cfg, final_B_kernel, out);
}

// round 15
// speedup vs baseline: 1.2092x; 1.0992x over previous
#include <cuda_runtime.h>

#define MB 32
#define NP 256
#define QP (NP / 2)
#define ND 512
#define NWORK (MB * MB + MB)        // 1056 worker blocks
#define NBLK (NWORK + 1)            // +1 finale block

// scratch (no allocations allowed)
__device__ float g_D[MB * MB];      // D(i,j) = mean_p min_q d2
__device__ float g_phat[MB * MB];   // softmax(inner_dot) rows, precomputed
__device__ int   g_counter;         // zero-init; finale resets each run

// ---- packed f32x2 helpers (Blackwell FFMA2 path) ---------------------------
__device__ __forceinline__ unsigned long long pack2(float lo, float hi) {
    unsigned long long r;
    asm("mov.b64 %0, {%1, %2};" : "=l"(r) : "f"(lo), "f"(hi));
    return r;
}
__device__ __forceinline__ unsigned long long fma2(unsigned long long a,
                                                   unsigned long long b,
                                                   unsigned long long c) {
    unsigned long long d;
    asm("fma.rn.f32x2 %0, %1, %2, %3;" : "=l"(d) : "l"(a), "l"(b), "l"(c));
    return d;
}
__device__ __forceinline__ void unpack2(unsigned long long v, float& lo, float& hi) {
    asm("mov.b64 {%0, %1}, %2;" : "=f"(lo), "=f"(hi) : "l"(v));
}

// release-add: makes all prior global writes of this thread visible to
// any thread that acquire-reads the counter afterwards. No return value.
__device__ __forceinline__ void red_release_add(int* addr, int val) {
    asm volatile("red.release.gpu.global.add.s32 [%0], %1;"
                 :: "l"(addr), "r"(val) : "memory");
}
__device__ __forceinline__ int ld_acquire(const int* addr) {
    int v;
    asm volatile("ld.acquire.gpu.global.s32 %0, [%1];"
                 : "=r"(v) : "l"(addr) : "memory");
    return v;
}

// ---------------------------------------------------------------------------
// Single kernel, 1057 blocks x 128 threads:
//   blocks [0,1024): chamfer D(i,j), ordered pair (i = b>>5, j = b&31)
//   blocks [1024,1056): inner_dot row i + softmax -> g_phat row
//   block 1056: finale — polls counter, then computes the scalar output.
// ---------------------------------------------------------------------------
__global__ void fused_kernel(const float* __restrict__ xyz,
                             const float* __restrict__ emb,
                             float* __restrict__ out) {
    const int b = blockIdx.x;
    const int t = threadIdx.x;          // 0..127
    const int w = t >> 5, lane = t & 31;

    if (b < MB * MB) {
        // ---------------- chamfer part ----------------
        const int i = b >> 5, j = b & 31;
        __shared__ float4 s_j[2 * QP];
        __shared__ float  s_red[4];

        const float* shapes = xyz + MB * NP * 3;

        // stage shape j pair-interleaved SoA: {x0,x1,y0,y1} | {z0,z1,w0,w1}
        for (int q = t; q < NP; q += 128) {
            const float* p = shapes + (j * NP + q) * 3;
            float x = p[0], y = p[1], z = p[2];
            float ww = x * x + y * y + z * z;
            float* base = reinterpret_cast<float*>(&s_j[(q >> 1) * 2]);
            int s = q & 1;
            base[0 + s] = x;
            base[2 + s] = y;
            base[4 + s] = z;
            base[6 + s] = ww;
        }

        // my 2 a-points, pre-scaled by -2, splatted to f32x2
        unsigned long long a2x[2], a2y[2], a2z[2];
        float aw[2];
#pragma unroll
        for (int k = 0; k < 2; k++) {
            const float* p = shapes + (i * NP + t + 128 * k) * 3;
            float x = p[0], y = p[1], z = p[2];
            aw[k] = x * x + y * y + z * z;
            a2x[k] = pack2(-2.f * x, -2.f * x);
            a2y[k] = pack2(-2.f * y, -2.f * y);
            a2z[k] = pack2(-2.f * z, -2.f * z);
        }

        __syncthreads();

        const float INF = 3.4e38f;
        float mlo[2] = {INF, INF};
        float mhi[2] = {INF, INF};

        const ulonglong2* sj64 = reinterpret_cast<const ulonglong2*>(s_j);

#pragma unroll 4
        for (int qp = 0; qp < QP; qp++) {
            ulonglong2 xy = sj64[2 * qp + 0];  // {x01, y01}
            ulonglong2 zw = sj64[2 * qp + 1];  // {z01, w01}
#pragma unroll
            for (int k = 0; k < 2; k++) {
                unsigned long long s =
                    fma2(a2x[k], xy.x, fma2(a2y[k], xy.y, fma2(a2z[k], zw.x, zw.y)));
                float lo, hi;
                unpack2(s, lo, hi);
                mlo[k] = fminf(mlo[k], lo);
                mhi[k] = fminf(mhi[k], hi);
            }
        }

        float s = fminf(mlo[0], mhi[0]) + aw[0] + fminf(mlo[1], mhi[1]) + aw[1];
#pragma unroll
        for (int o = 16; o > 0; o >>= 1) s += __shfl_down_sync(0xffffffffu, s, o);
        if (lane == 0) s_red[w] = s;
        __syncthreads();
        if (t == 0) {
            g_D[i * MB + j] = (s_red[0] + s_red[1] + s_red[2] + s_red[3]) * (1.f / NP);
            red_release_add(&g_counter, 1);
        }
    } else if (b < NWORK) {
        // ---------------- inner_dot row + p_hat softmax ----------------
        const int i = b - MB * MB;
        __shared__ float s_dot[MB];

        // keep my slice of emb row i in registers, reuse for all j
        float eir[16];
        float ni = 0.f;
#pragma unroll
        for (int u = 0; u < 16; u++) {
            float e = emb[i * ND + u * 32 + lane];
            eir[u] = e;
            ni += e * e;
        }
#pragma unroll
        for (int o = 16; o > 0; o >>= 1) ni += __shfl_xor_sync(0xffffffffu, ni, o);
        const float inv_ni = rsqrtf(ni);

        for (int j = w; j < MB; j += 4) {
            const float* ej = emb + (MB + j) * ND;
            float dot = 0.f, nj = 0.f;
#pragma unroll
            for (int u = 0; u < 16; u++) {
                float e = ej[u * 32 + lane];
                dot += e * eir[u];
                nj += e * e;
            }
#pragma unroll
            for (int o = 16; o > 0; o >>= 1) {
                dot += __shfl_down_sync(0xffffffffu, dot, o);
                nj  += __shfl_down_sync(0xffffffffu, nj, o);
            }
            if (lane == 0) s_dot[j] = dot * rsqrtf(nj) * inv_ni;
        }
        __syncthreads();

        // warp 0: softmax over the 32 dots -> p_hat row, then signal
        if (w == 0) {
            float idot = s_dot[lane];
            float m = idot;
#pragma unroll
            for (int o = 16; o > 0; o >>= 1) m = fmaxf(m, __shfl_xor_sync(0xffffffffu, m, o));
            float e = expf(idot - m);
            float sum = e;
#pragma unroll
            for (int o = 16; o > 0; o >>= 1) sum += __shfl_xor_sync(0xffffffffu, sum, o);
            g_phat[i * MB + lane] = e / sum;
            if (lane == 0) red_release_add(&g_counter, 1);
        }
    } else {
        // ---------------- finale block: poll, then reduce ----------------
        if (t == 0) {
            while (ld_acquire(&g_counter) < NWORK) {
                __nanosleep(64);
            }
        }
        __syncthreads();   // all 128 threads now see completed g_D / g_phat

        __shared__ float s_row[MB];
        const float SIG = 1.0f * 0.997f / 3.0f;
        const float INV2S2 = 1.0f / (2.0f * SIG * SIG);

        // 4 warps x 8 rows each
#pragma unroll
        for (int r = 0; r < 8; r++) {
            const int i = w * 8 + r;

            float p_hat = g_phat[i * MB + lane];
            float cd = g_D[i * MB + lane] + g_D[lane * MB + i];
            float nd = -(cd * cd) * INV2S2;
            float m2 = nd;
#pragma unroll
            for (int o = 16; o > 0; o >>= 1) m2 = fmaxf(m2, __shfl_xor_sync(0xffffffffu, m2, o));
            float e2 = expf(nd - m2);
            float sum2 = e2;
#pragma unroll
            for (int o = 16; o > 0; o >>= 1) sum2 += __shfl_xor_sync(0xffffffffu, sum2, o);
            float p = e2 / sum2;

            float diff = fabsf(p_hat - p);
#pragma unroll
            for (int o = 16; o > 0; o >>= 1) diff += __shfl_xor_sync(0xffffffffu, diff, o);
            if (lane == 0) s_row[i] = diff;
        }
        __syncthreads();

        if (w == 0) {
            float v = s_row[lane];
#pragma unroll
            for (int o = 16; o > 0; o >>= 1) v += __shfl_down_sync(0xffffffffu, v, o);
            if (lane == 0) {
                out[0] = v * (1.0f / (MB * MB));
                g_counter = 0;  // reset for next graph replay
            }
        }
    }
}

extern "C" void kernel_launch(void* const* d_in, const int* in_sizes, int n_in,
                              void* d_out, int out_size) {
    const float* embeddings = (const float*)d_in[0];  // (64, 512) fp32
    const float* xyz        = (const float*)d_in[1];  // (64, 256, 3) fp32
    float* out = (float*)d_out;

    fused_kernel<<<NBLK, 128>>>(xyz, embeddings, out);
}

// round 16
// speedup vs baseline: 1.3378x; 1.1064x over previous
#include <cuda_runtime.h>

#define MB 32
#define NP 256
#define QP (NP / 2)
#define ND 512

// scratch (no allocations allowed)
__device__ float g_D[MB * MB];      // D(i,j) = mean_p min_q d2
__device__ float g_Dt[MB * MB];     // transposed copy: g_Dt[j][i] = D(i,j)
__device__ float g_phat[MB * MB];   // softmax(inner_dot) rows, precomputed

// ---- packed f32x2 helpers (Blackwell FFMA2 path) ---------------------------
__device__ __forceinline__ unsigned long long pack2(float lo, float hi) {
    unsigned long long r;
    asm("mov.b64 %0, {%1, %2};" : "=l"(r) : "f"(lo), "f"(hi));
    return r;
}
__device__ __forceinline__ unsigned long long fma2(unsigned long long a,
                                                   unsigned long long b,
                                                   unsigned long long c) {
    unsigned long long d;
    asm("fma.rn.f32x2 %0, %1, %2, %3;" : "=l"(d) : "l"(a), "l"(b), "l"(c));
    return d;
}
__device__ __forceinline__ void unpack2(unsigned long long v, float& lo, float& hi) {
    asm("mov.b64 {%0, %1}, %2;" : "=f"(lo), "=f"(hi) : "l"(v));
}

// ---------------------------------------------------------------------------
// Kernel A, flat grid of 1056 blocks x 128 threads:
//   blocks [0,1024): chamfer D(i,j) for ordered pair (i = b>>5, j = b&31)
//   blocks [1024,1056): inner_dot row i + its softmax -> g_phat row
// ---------------------------------------------------------------------------
__global__ void __launch_bounds__(128)
fused_A_kernel(const float* __restrict__ xyz,
               const float* __restrict__ emb) {
    const int b = blockIdx.x;
    const int t = threadIdx.x;          // 0..127
    const int w = t >> 5, lane = t & 31;

    if (b < MB * MB) {
        // ---------------- chamfer part ----------------
        const int i = b >> 5, j = b & 31;
        __shared__ float4 s_j[2 * QP];
        __shared__ float  s_red[4];

        const float* shapes = xyz + MB * NP * 3;

        // stage shape j pair-interleaved SoA: {x0,x1,y0,y1} | {z0,z1,w0,w1}
        for (int q = t; q < NP; q += 128) {
            const float* p = shapes + (j * NP + q) * 3;
            float x = p[0], y = p[1], z = p[2];
            float ww = x * x + y * y + z * z;
            float* base = reinterpret_cast<float*>(&s_j[(q >> 1) * 2]);
            int s = q & 1;
            base[0 + s] = x;
            base[2 + s] = y;
            base[4 + s] = z;
            base[6 + s] = ww;
        }

        // my 2 a-points, pre-scaled by -2, splatted to f32x2
        unsigned long long a2x[2], a2y[2], a2z[2];
        float aw[2];
#pragma unroll
        for (int k = 0; k < 2; k++) {
            const float* p = shapes + (i * NP + t + 128 * k) * 3;
            float x = p[0], y = p[1], z = p[2];
            aw[k] = x * x + y * y + z * z;
            a2x[k] = pack2(-2.f * x, -2.f * x);
            a2y[k] = pack2(-2.f * y, -2.f * y);
            a2z[k] = pack2(-2.f * z, -2.f * z);
        }

        __syncthreads();

        const float INF = 3.4e38f;
        float mlo[2] = {INF, INF};
        float mhi[2] = {INF, INF};

        const ulonglong2* sj64 = reinterpret_cast<const ulonglong2*>(s_j);

#pragma unroll 8
        for (int qp = 0; qp < QP; qp++) {
            ulonglong2 xy = sj64[2 * qp + 0];  // {x01, y01}
            ulonglong2 zw = sj64[2 * qp + 1];  // {z01, w01}
#pragma unroll
            for (int k = 0; k < 2; k++) {
                unsigned long long s =
                    fma2(a2x[k], xy.x, fma2(a2y[k], xy.y, fma2(a2z[k], zw.x, zw.y)));
                float lo, hi;
                unpack2(s, lo, hi);
                mlo[k] = fminf(mlo[k], lo);
                mhi[k] = fminf(mhi[k], hi);
            }
        }

        float s = fminf(mlo[0], mhi[0]) + aw[0] + fminf(mlo[1], mhi[1]) + aw[1];
#pragma unroll
        for (int o = 16; o > 0; o >>= 1) s += __shfl_down_sync(0xffffffffu, s, o);
        if (lane == 0) s_red[w] = s;
        __syncthreads();
        if (t == 0) {
            float d = (s_red[0] + s_red[1] + s_red[2] + s_red[3]) * (1.f / NP);
            g_D[i * MB + j]  = d;
            g_Dt[j * MB + i] = d;
        }
    } else {
        // ---------------- inner_dot row + p_hat softmax ----------------
        const int i = b - MB * MB;
        __shared__ float s_dot[MB];

        // keep my slice of emb row i in registers, reuse for all j
        float eir[16];
        float ni = 0.f;
#pragma unroll
        for (int u = 0; u < 16; u++) {
            float e = emb[i * ND + u * 32 + lane];
            eir[u] = e;
            ni += e * e;
        }
#pragma unroll
        for (int o = 16; o > 0; o >>= 1) ni += __shfl_xor_sync(0xffffffffu, ni, o);
        const float inv_ni = rsqrtf(ni);

        for (int j = w; j < MB; j += 4) {
            const float* ej = emb + (MB + j) * ND;
            float dot = 0.f, nj = 0.f;
#pragma unroll
            for (int u = 0; u < 16; u++) {
                float e = ej[u * 32 + lane];
                dot += e * eir[u];
                nj += e * e;
            }
#pragma unroll
            for (int o = 16; o > 0; o >>= 1) {
                dot += __shfl_down_sync(0xffffffffu, dot, o);
                nj  += __shfl_down_sync(0xffffffffu, nj, o);
            }
            if (lane == 0) s_dot[j] = dot * rsqrtf(nj) * inv_ni;
        }
        __syncthreads();

        // warp 0: softmax over the 32 dots -> p_hat row
        if (w == 0) {
            float idot = s_dot[lane];
            float m = idot;
#pragma unroll
            for (int o = 16; o > 0; o >>= 1) m = fmaxf(m, __shfl_xor_sync(0xffffffffu, m, o));
            float e = expf(idot - m);
            float sum = e;
#pragma unroll
            for (int o = 16; o > 0; o >>= 1) sum += __shfl_xor_sync(0xffffffffu, sum, o);
            g_phat[i * MB + lane] = e / sum;
        }
    }
}

// ---------------------------------------------------------------------------
// Kernel B: 1 block x 1024 threads. Warp i handles row i:
// cd softmax -> p; |p_hat - p| row sum. Warp 0 does the final sum.
// All loads coalesced (g_Dt supplies the transposed column as a row).
// ---------------------------------------------------------------------------
__global__ void final_B_kernel(float* __restrict__ out) {
    __shared__ float s_row[MB];
    const int i = threadIdx.x >> 5, lane = threadIdx.x & 31;

    {
        float p_hat = g_phat[i * MB + lane];

        const float SIG = 1.0f * 0.997f / 3.0f;
        const float INV2S2 = 1.0f / (2.0f * SIG * SIG);
        float cd = g_D[i * MB + lane] + g_Dt[i * MB + lane];
        float nd = -(cd * cd) * INV2S2;
        float m2 = nd;
#pragma unroll
        for (int o = 16; o > 0; o >>= 1) m2 = fmaxf(m2, __shfl_xor_sync(0xffffffffu, m2, o));
        float e2 = expf(nd - m2);
        float sum2 = e2;
#pragma unroll
        for (int o = 16; o > 0; o >>= 1) sum2 += __shfl_xor_sync(0xffffffffu, sum2, o);
        float p = e2 / sum2;

        float diff = fabsf(p_hat - p);
#pragma unroll
        for (int o = 16; o > 0; o >>= 1) diff += __shfl_xor_sync(0xffffffffu, diff, o);
        if (lane == 0) s_row[i] = diff;
    }
    __syncthreads();

    if (i == 0) {
        float v = s_row[lane];
#pragma unroll
        for (int o = 16; o > 0; o >>= 1) v += __shfl_down_sync(0xffffffffu, v, o);
        if (lane == 0) out[0] = v * (1.0f / (MB * MB));
    }
}

extern "C" void kernel_launch(void* const* d_in, const int* in_sizes, int n_in,
                              void* d_out, int out_size) {
    const float* embeddings = (const float*)d_in[0];  // (64, 512) fp32
    const float* xyz        = (const float*)d_in[1];  // (64, 256, 3) fp32
    float* out = (float*)d_out;

    fused_A_kernel<<<MB * MB + MB, 128>>>(xyz, embeddings);
    final_B_kernel<<<1, MB * 32>>>(out);
}